// round 15
// baseline (speedup 1.0000x reference)
#include <cuda_runtime.h>
#include <cuda_fp16.h>
#include <cstddef>
#include <cstdint>

#define H 64
#define NGn 100000
#define NDn 30000
#define Mn (NGn + NDn)
#define NEmax 1500000
#define SCAN_B 1024
#define NBLK ((Mn + SCAN_B - 1) / SCAN_B)   // 127
#define NBD ((NDn + 127) / 128)             // 235
#define NBG ((NGn + 127) / 128)             // 782

// -------- scratch (zero-initialized at module load).
// Invariant: g_deg/g_partf zero at every kernel_launch entry; dot_h restores. --
__device__ int   g_deg [Mn];
__device__ int   g_partf[128];
__device__ int   g_off [Mn + 1];
__device__ int   g_cur [Mn];
__device__ __align__(16) int g_adj [2 * NEmax + 4 * Mn];  // byte offsets; padded to 4/node
// gatherable tables carry ONE extra all-zero sentinel row (never written)
__device__ __half2 g_geneH[(size_t)(NGn + 1) * 32];
__device__ __half2 g_disH [(size_t)(NDn + 1) * 32];
__device__ __half2 g_hgH  [(size_t)(NGn + 1) * 32];
__device__ __half2 g_hdH  [(size_t)(NDn + 1) * 32];
__device__ __half2 g_mGH  [(size_t)NGn * 32];    // layer-2 outputs (dot inputs)
__device__ __half2 g_mDH  [(size_t)NDn * 32];
__device__ uint2   g_wPack[4 * 2048];

// -------- helpers --------
__device__ __forceinline__ uint32_t packh2(float a, float b) {
    __half2 h = __floats2half2_rn(a, b);
    return *reinterpret_cast<uint32_t*>(&h);
}
__device__ __forceinline__ void mma16(float c[4],
                                      uint32_t a0, uint32_t a1, uint32_t a2, uint32_t a3,
                                      uint32_t b0, uint32_t b1) {
    asm volatile(
        "mma.sync.aligned.m16n8k16.row.col.f32.f16.f16.f32 "
        "{%0,%1,%2,%3},{%4,%5,%6,%7},{%8,%9},{%0,%1,%2,%3};"
        : "+f"(c[0]), "+f"(c[1]), "+f"(c[2]), "+f"(c[3])
        : "r"(a0), "r"(a1), "r"(a2), "r"(a3), "r"(b0), "r"(b1));
}
__device__ __forceinline__ void accx2(unsigned long long& acc, __half2 h) {
    float2 f = __half22float2(h);
    unsigned long long v;
    asm("mov.b64 %0, {%1, %2};" : "=l"(v) : "f"(f.x), "f"(f.y));
    asm("add.rn.f32x2 %0, %0, %1;" : "+l"(acc) : "l"(v));
}
__device__ __forceinline__ void acc_u4_pair_x2(unsigned long long* aa, uint4 v0, uint4 v1) {
    const __half2* h0 = (const __half2*)&v0;
    const __half2* h1 = (const __half2*)&v1;
    accx2(aa[0], __hadd2(h0[0], h1[0]));
    accx2(aa[1], __hadd2(h0[1], h1[1]));
    accx2(aa[2], __hadd2(h0[2], h1[2]));
    accx2(aa[3], __hadd2(h0[3], h1[3]));
}

// -------- fused prep (f2h + weight packing) + hist, block-range split --------
#define NG2   (NGn * 32)
#define ND2   (NDn * 32)
#define NWP   (4 * 2048)
#define PREP_ITEMS (NG2 + ND2 + NWP)
#define PREP_BLOCKS ((PREP_ITEMS + 255) / 256)
__global__ __launch_bounds__(256) void prep_hist(
    const float2* __restrict__ gene, __half2* __restrict__ geneH,
    const float2* __restrict__ dis,  __half2* __restrict__ disH,
    const float* __restrict__ w0, const float* __restrict__ w1,
    const float* __restrict__ w2, const float* __restrict__ w3,
    const float* __restrict__ w4, const float* __restrict__ w5,
    const float* __restrict__ w6, const float* __restrict__ w7,
    uint2* __restrict__ wPack,
    const int* __restrict__ src, const int* __restrict__ dst, int ne)
{
    int blk = blockIdx.x;
    if (blk < PREP_BLOCKS) {
        int i = blk * 256 + threadIdx.x;
        if (i < NG2) {
            float2 v = gene[i];
            geneH[i] = __floats2half2_rn(v.x, v.y);
        } else if (i < NG2 + ND2) {
            int j = i - NG2;
            float2 v = dis[j];
            disH[j] = __floats2half2_rn(v.x, v.y);
        } else if (i < PREP_ITEMS) {
            int p = i - (NG2 + ND2);
            int pi  = p >> 11;
            int rem = p & 2047;
            const float* wl;
            const float* wr;
            if      (pi == 0) { wl = w0; wr = w1; }
            else if (pi == 1) { wl = w2; wr = w3; }
            else if (pi == 2) { wl = w4; wr = w5; }
            else              { wl = w6; wr = w7; }
            int kc   = rem >> 8;
            int nt   = (rem >> 5) & 7;
            int lane = rem & 31;
            int t = lane & 3, g = lane >> 2;
            int c = nt * 8 + g;
            int k0 = kc * 16;
            int r0 = k0 + 2 * t, r2 = r0 + 8;
            float w00 = (r0 < 64)     ? wl[r0 * 64 + c]       : wr[(r0 - 64) * 64 + c];
            float w01 = (r0 + 1 < 64) ? wl[(r0 + 1) * 64 + c] : wr[(r0 - 63) * 64 + c];
            float w10 = (r2 < 64)     ? wl[r2 * 64 + c]       : wr[(r2 - 64) * 64 + c];
            float w11 = (r2 + 1 < 64) ? wl[(r2 + 1) * 64 + c] : wr[(r2 - 63) * 64 + c];
            wPack[p] = make_uint2(packh2(w00, w01), packh2(w10, w11));
        }
    } else {
        int e = (blk - PREP_BLOCKS) * 256 + threadIdx.x;
        if (e < ne) {
            atomicAdd(&g_deg[src[e]], 1);
            atomicAdd(&g_deg[NGn + dst[e]], 1);
        }
    }
}

// -------- single-pass scan (padded to 4/node) + sentinel fill --------
__global__ __launch_bounds__(1024) void scan_fused(
    int* __restrict__ off, int* __restrict__ cur, int* __restrict__ adj, int n)
{
    __shared__ int ws[32];
    __shared__ int sv[128];
    __shared__ int sExc;
    int bid = blockIdx.x;
    int tid = threadIdx.x;
    int i = bid * SCAN_B + tid;
    int v = (i < n) ? g_deg[i] : 0;
    int vp = (v + 3) & ~3;
    int x = vp;
    #pragma unroll
    for (int o = 1; o < 32; o <<= 1) {
        int y = __shfl_up_sync(0xFFFFFFFFu, x, o);
        if ((tid & 31) >= o) x += y;
    }
    if ((tid & 31) == 31) ws[tid >> 5] = x;
    __syncthreads();
    if (tid < 32) {
        int y = ws[tid];
        #pragma unroll
        for (int o = 1; o < 32; o <<= 1) {
            int z = __shfl_up_sync(0xFFFFFFFFu, y, o);
            if (tid >= o) y += z;
        }
        ws[tid] = y;
    }
    __syncthreads();
    if (tid >= 32) x += ws[(tid >> 5) - 1];
    if (tid == 1023) {
        atomicExch(&g_partf[bid], (x << 1) | 1);
    }
    if (tid < 128) sv[tid] = 0;
    __syncthreads();
    if (tid < bid) {
        int p;
        do { p = *(volatile int*)&g_partf[tid]; } while ((p & 1) == 0);
        sv[tid] = p >> 1;
    }
    __syncthreads();
    if (tid < 64) sv[tid] += sv[tid + 64];
    __syncthreads();
    if (tid < 32) {
        int s = sv[tid] + sv[tid + 32];
        #pragma unroll
        for (int o = 16; o; o >>= 1) s += __shfl_down_sync(0xFFFFFFFFu, s, o);
        if (tid == 0) sExc = s;
    }
    __syncthreads();
    if (i < n) {
        int inc = x + sExc;
        off[i + 1] = inc;
        int start = inc - vp;
        cur[i] = start;
        int sent = (i < NGn) ? (NDn << 7) : (NGn << 7);
        for (int k = v; k < vp; k++) adj[start + k] = sent;
        if (i == 0) off[0] = 0;
    }
}

// -------- scatter (stores PRE-SCALED byte offsets) --------
__global__ void scatter_kernel(const int* __restrict__ src, const int* __restrict__ dst,
                               int* __restrict__ cur, int* __restrict__ adj, int ne) {
    int e = blockIdx.x * blockDim.x + threadIdx.x;
    if (e < ne) {
        int s = src[e], d = dst[e];
        int p = atomicAdd(&cur[s], 1);        adj[p] = d << 7;
        int q = atomicAdd(&cur[NGn + d], 1);  adj[q] = s << 7;
    }
}

// -------- FUSED gather + SAGE linear per layer --------
// Per 128-node tile: 8 warps (4 nodes each, 8-lane groups) gather means
// DIRECTLY into sA; then staged fp16 MMA (mean kc0-3, x kc4-7) + epilogue.
// Grid split D/G by work (edges are equal both directions -> ~half/half).
#define LIN_GRID 592
__global__ __launch_bounds__(256) void gmma(
    const char* __restrict__ gsD, const char* __restrict__ gsG,   // gather sources
    const char* __restrict__ xDt, const char* __restrict__ xGt,   // self tables
    const uint2* __restrict__ wp,                                  // layer base: D@0, G@2048
    const float* __restrict__ bD, const float* __restrict__ bG,
    __half2* __restrict__ outD, __half2* __restrict__ outG,
    int relu)
{
    __shared__ uint2 sB[2048];
    __shared__ float sBias[64];
    __shared__ uint32_t sA[128][36];

    int split = LIN_GRID / 2;   // equal edge work both directions
    bool isD = (int)blockIdx.x < split;
    int n            = isD ? NDn : NGn;
    int nodeBase     = isD ? NGn : 0;
    const char* gsrc = isD ? gsD : gsG;
    const uint4* xsrc = (const uint4*)(isD ? xDt : xGt);
    __half2* out_h   = isD ? outD : outG;
    const uint2* wps = wp + (isD ? 0 : 2048);
    const float* bias = isD ? bD : bG;
    int nTiles = isD ? NBD : NBG;
    int blk0   = isD ? blockIdx.x : (blockIdx.x - split);
    int nSeg   = isD ? split : (LIN_GRID - split);

    int tid = threadIdx.x;
    for (int i = tid; i < 2048; i += 256) sB[i] = __ldg(&wps[i]);
    if (tid < 64) sBias[tid] = bias[tid];

    int warp = tid >> 5, lane = tid & 31;
    int grp = (tid >> 3) & 3, l = tid & 7;      // gather coords
    int t = lane & 3, g2 = lane >> 2;           // mma fragment coords
    int la = warp * 16 + g2, lb = la + 8;
    const char* __restrict__ xb = gsrc + (l << 4);

    for (int blk = blk0; blk < nTiles; blk += nSeg) {
        int rowBase = blk * 128;

        __syncthreads();   // prev tile's sA reads done (covers sB/sBias first iter)

        // ---- gather mean tile straight into sA ----
        for (int p = 0; p < 4; p++) {
            int row = warp * 16 + p * 4 + grp;
            int wl = rowBase + row;
            uint4 o = make_uint4(0u, 0u, 0u, 0u);
            if (wl < n) {
                int gid = nodeBase + wl;
                int beg = __ldg(&g_off[gid]);
                int end = __ldg(&g_off[gid + 1]);
                int dg  = __ldg(&g_deg[gid]);
                const int4* __restrict__ a4 = (const int4*)(g_adj + beg);
                int trips = (end - beg) >> 2;
                unsigned long long aa[4];
                {
                    unsigned long long z;
                    asm("mov.b64 %0, {%1, %2};" : "=l"(z) : "f"(0.0f), "f"(0.0f));
                    aa[0] = z; aa[1] = z; aa[2] = z; aa[3] = z;
                }
                int qi = 0;
                for (; qi + 2 <= trips; qi += 2) {
                    int4 q0 = __ldg(&a4[qi]);
                    int4 q1 = __ldg(&a4[qi + 1]);
                    uint4 v0 = *(const uint4*)(xb + q0.x);
                    uint4 v1 = *(const uint4*)(xb + q0.y);
                    uint4 v2 = *(const uint4*)(xb + q0.z);
                    uint4 v3 = *(const uint4*)(xb + q0.w);
                    uint4 v4 = *(const uint4*)(xb + q1.x);
                    uint4 v5 = *(const uint4*)(xb + q1.y);
                    uint4 v6 = *(const uint4*)(xb + q1.z);
                    uint4 v7 = *(const uint4*)(xb + q1.w);
                    acc_u4_pair_x2(aa, v0, v1);
                    acc_u4_pair_x2(aa, v2, v3);
                    acc_u4_pair_x2(aa, v4, v5);
                    acc_u4_pair_x2(aa, v6, v7);
                }
                if (qi < trips) {
                    int4 q = __ldg(&a4[qi]);
                    uint4 v0 = *(const uint4*)(xb + q.x);
                    uint4 v1 = *(const uint4*)(xb + q.y);
                    uint4 v2 = *(const uint4*)(xb + q.z);
                    uint4 v3 = *(const uint4*)(xb + q.w);
                    acc_u4_pair_x2(aa, v0, v1);
                    acc_u4_pair_x2(aa, v2, v3);
                }
                float2 a0, a1, a2, a3;
                asm("mov.b64 {%0, %1}, %2;" : "=f"(a0.x), "=f"(a0.y) : "l"(aa[0]));
                asm("mov.b64 {%0, %1}, %2;" : "=f"(a1.x), "=f"(a1.y) : "l"(aa[1]));
                asm("mov.b64 {%0, %1}, %2;" : "=f"(a2.x), "=f"(a2.y) : "l"(aa[2]));
                asm("mov.b64 {%0, %1}, %2;" : "=f"(a3.x), "=f"(a3.y) : "l"(aa[3]));
                float inv = 1.0f / fmaxf((float)dg, 1.0f);
                o.x = packh2(a0.x * inv, a0.y * inv);
                o.y = packh2(a1.x * inv, a1.y * inv);
                o.z = packh2(a2.x * inv, a2.y * inv);
                o.w = packh2(a3.x * inv, a3.y * inv);
            }
            *(uint4*)&sA[row][l * 4] = o;
        }
        __syncthreads();

        // ---- mma: mean half (kc 0-3) ----
        float c_[8][4];
        #pragma unroll
        for (int nt = 0; nt < 8; nt++) {
            float b0 = sBias[nt * 8 + 2 * t];
            float b1 = sBias[nt * 8 + 2 * t + 1];
            c_[nt][0] = b0; c_[nt][1] = b1; c_[nt][2] = b0; c_[nt][3] = b1;
        }
        #pragma unroll
        for (int kc = 0; kc < 4; kc++) {
            int b8 = kc * 8;
            uint32_t a0 = sA[la][b8 + t];
            uint32_t a1 = sA[lb][b8 + t];
            uint32_t a2 = sA[la][b8 + t + 4];
            uint32_t a3 = sA[lb][b8 + t + 4];
            #pragma unroll
            for (int nt = 0; nt < 8; nt++) {
                uint2 B = sB[kc * 256 + nt * 32 + lane];
                mma16(c_[nt], a0, a1, a2, a3, B.x, B.y);
            }
        }
        __syncthreads();

        // ---- stage x tile, mma kc 4-7 ----
        #pragma unroll
        for (int r4 = 0; r4 < 4; r4++) {
            int flat = tid + r4 * 256;
            int row = flat >> 3, c4 = flat & 7;
            int gr = rowBase + row;
            uint4 v = __ldg(&xsrc[(size_t)(gr < n ? gr : 0) * 8 + c4]);
            *(uint4*)&sA[row][c4 * 4] = v;
        }
        __syncthreads();

        #pragma unroll
        for (int kc = 4; kc < 8; kc++) {
            int b8 = (kc & 3) * 8;
            uint32_t a0 = sA[la][b8 + t];
            uint32_t a1 = sA[lb][b8 + t];
            uint32_t a2 = sA[la][b8 + t + 4];
            uint32_t a3 = sA[lb][b8 + t + 4];
            #pragma unroll
            for (int nt = 0; nt < 8; nt++) {
                uint2 B = sB[kc * 256 + nt * 32 + lane];
                mma16(c_[nt], a0, a1, a2, a3, B.x, B.y);
            }
        }

        // ---- epilogue ----
        int ra = rowBase + la, rb = rowBase + lb;
        bool va = ra < n, vb = rb < n;
        #pragma unroll
        for (int nt = 0; nt < 8; nt++) {
            float c0 = c_[nt][0], c1 = c_[nt][1], c2 = c_[nt][2], c3 = c_[nt][3];
            if (relu) {
                c0 = fmaxf(c0, 0.f); c1 = fmaxf(c1, 0.f);
                c2 = fmaxf(c2, 0.f); c3 = fmaxf(c3, 0.f);
            }
            if (va) out_h[(size_t)ra * 32 + nt * 4 + t] = __floats2half2_rn(c0, c1);
            if (vb) out_h[(size_t)rb * 32 + nt * 4 + t] = __floats2half2_rn(c2, c3);
        }
    }
}

// -------- label-edge dot product + restore deg/partf zero-invariant --------
__global__ __launch_bounds__(256) void dot_h(
    const __half2* __restrict__ hg2, const __half2* __restrict__ hd2,
    const int* __restrict__ ls, const int* __restrict__ ld,
    float* __restrict__ out, int nl)
{
    int t = blockIdx.x * blockDim.x + threadIdx.x;
    if (t < Mn) g_deg[t] = 0;
    if (t < 128) g_partf[t] = 0;
    int e = t >> 3;
    if (e >= nl) return;
    int lane = t & 7;
    int a = ls[e];
    int b = ld[e];
    const uint4* pg = (const uint4*)(hg2 + (size_t)a * 32);
    const uint4* pd = (const uint4*)(hd2 + (size_t)b * 32);
    uint4 G = __ldg(&pg[lane]);
    uint4 D = __ldg(&pd[lane]);

    float acc = 0.f;
    {
        float2 g0 = __half22float2(*(__half2*)&G.x), d0 = __half22float2(*(__half2*)&D.x);
        float2 g1 = __half22float2(*(__half2*)&G.y), d1 = __half22float2(*(__half2*)&D.y);
        float2 g2 = __half22float2(*(__half2*)&G.z), d2 = __half22float2(*(__half2*)&D.z);
        float2 g3 = __half22float2(*(__half2*)&G.w), d3 = __half22float2(*(__half2*)&D.w);
        acc = g0.x * d0.x + g0.y * d0.y + g1.x * d1.x + g1.y * d1.y
            + g2.x * d2.x + g2.y * d2.y + g3.x * d3.x + g3.y * d3.y;
    }
    acc += __shfl_down_sync(0xFFFFFFFFu, acc, 4);
    acc += __shfl_down_sync(0xFFFFFFFFu, acc, 2);
    acc += __shfl_down_sync(0xFFFFFFFFu, acc, 1);
    if (lane == 0) out[e] = acc;
}

extern "C" void kernel_launch(void* const* d_in, const int* in_sizes, int n_in,
                              void* d_out, int out_size)
{
    const float* gene = nullptr;
    const float* dis  = nullptr;
    const float* w[8] = {};
    const float* b[4] = {};
    const int*   edge[2] = {};
    const int*   lab[2]  = {};
    int wi = 0, bi = 0, ei = 0, li = 0;
    int ne = 0, nl = 0;

    for (int i = 0; i < n_in; i++) {
        int sz = in_sizes[i];
        if (sz == NGn * H)          gene = (const float*)d_in[i];
        else if (sz == NDn * H)     dis  = (const float*)d_in[i];
        else if (sz == H * H)       { if (wi < 8) w[wi++] = (const float*)d_in[i]; }
        else if (sz == H)           { if (bi < 4) b[bi++] = (const float*)d_in[i]; }
        else if (sz == 1500000)     { if (ei < 2) { edge[ei++] = (const int*)d_in[i]; ne = sz; } }
        else if (sz == 500000)      { if (li < 2) { lab[li++]  = (const int*)d_in[i]; nl = sz; } }
    }

    int *off, *cur, *adj;
    __half2 *geneH, *disH, *hgH, *hdH, *mGH, *mDH;
    uint2 *wPack;
    cudaGetSymbolAddress((void**)&off,   g_off);
    cudaGetSymbolAddress((void**)&cur,   g_cur);
    cudaGetSymbolAddress((void**)&adj,   g_adj);
    cudaGetSymbolAddress((void**)&geneH, g_geneH);
    cudaGetSymbolAddress((void**)&disH,  g_disH);
    cudaGetSymbolAddress((void**)&hgH,   g_hgH);
    cudaGetSymbolAddress((void**)&hdH,   g_hdH);
    cudaGetSymbolAddress((void**)&mGH,   g_mGH);
    cudaGetSymbolAddress((void**)&mDH,   g_mDH);
    cudaGetSymbolAddress((void**)&wPack, g_wPack);

    int egrid = (ne + 255) / 256;
    int ph_grid = PREP_BLOCKS + egrid;

    // ---- fused prep+hist -> padded scan (+sentinels) -> scatter ----
    prep_hist<<<ph_grid, 256>>>(
        (const float2*)gene, geneH, (const float2*)dis, disH,
        w[0], w[1], w[2], w[3], w[4], w[5], w[6], w[7], wPack,
        edge[0], edge[1], ne);
    scan_fused<<<NBLK, 1024>>>(off, cur, adj, Mn);
    scatter_kernel<<<egrid, 256>>>(edge[0], edge[1], cur, adj, ne);

    // ---- layer 1: fused gather+linear (D gathers gene rows, G gathers dis rows) ----
    gmma<<<LIN_GRID, 256>>>(
        (const char*)geneH, (const char*)disH,
        (const char*)disH,  (const char*)geneH,
        wPack, b[0], b[1], hdH, hgH, 1);

    // ---- layer 2: sources hgH/hdH, outputs mDH/mGH (no aliasing) ----
    gmma<<<LIN_GRID, 256>>>(
        (const char*)hgH, (const char*)hdH,
        (const char*)hdH, (const char*)hgH,
        wPack + 4096, b[2], b[3], mDH, mGH, 0);

    // ---- classifier (also restores deg/partf invariants) ----
    int dot_grid = (nl * 8 + 255) / 256;
    dot_h<<<dot_grid, 256>>>(mGH, mDH, lab[0], lab[1], (float*)d_out, nl);
}

// round 16
// speedup vs baseline: 1.0201x; 1.0201x over previous
#include <cuda_runtime.h>
#include <cuda_fp16.h>
#include <cstddef>
#include <cstdint>

#define H 64
#define NGn 100000
#define NDn 30000
#define Mn (NGn + NDn)
#define NEmax 1500000
#define SCAN_B 1024
#define NBLK ((Mn + SCAN_B - 1) / SCAN_B)   // 127

// -------- scratch (zero-initialized at module load).
// Invariant: g_deg/g_partf are zero at every kernel_launch entry; the LAST
// kernel (dot_h) restores this each call (g_deg is needed by the gathers). ----
__device__ int   g_deg [Mn];
__device__ int   g_partf[128];
__device__ int   g_off [Mn + 1];
__device__ int   g_cur [Mn];
__device__ __align__(16) int g_adj [2 * NEmax + 4 * Mn];  // byte offsets; padded to 4/node
// feature tables carry ONE extra all-zero sentinel row (never written)
__device__ __half2 g_geneH[(size_t)(NGn + 1) * 32];
__device__ __half2 g_disH [(size_t)(NDn + 1) * 32];
__device__ __half2 g_hgH  [(size_t)(NGn + 1) * 32];
__device__ __half2 g_hdH  [(size_t)(NDn + 1) * 32];
__device__ __half2 g_mGH  [(size_t)NGn * 32];
__device__ __half2 g_mDH  [(size_t)NDn * 32];
__device__ uint2   g_wPack[4 * 2048];

// -------- helpers --------
__device__ __forceinline__ uint32_t packh2(float a, float b) {
    __half2 h = __floats2half2_rn(a, b);
    return *reinterpret_cast<uint32_t*>(&h);
}
__device__ __forceinline__ void mma16(float c[4],
                                      uint32_t a0, uint32_t a1, uint32_t a2, uint32_t a3,
                                      uint32_t b0, uint32_t b1) {
    asm volatile(
        "mma.sync.aligned.m16n8k16.row.col.f32.f16.f16.f32 "
        "{%0,%1,%2,%3},{%4,%5,%6,%7},{%8,%9},{%0,%1,%2,%3};"
        : "+f"(c[0]), "+f"(c[1]), "+f"(c[2]), "+f"(c[3])
        : "r"(a0), "r"(a1), "r"(a2), "r"(a3), "r"(b0), "r"(b1));
}
__device__ __forceinline__ void accx2(unsigned long long& acc, __half2 h) {
    float2 f = __half22float2(h);
    unsigned long long v;
    asm("mov.b64 %0, {%1, %2};" : "=l"(v) : "f"(f.x), "f"(f.y));
    asm("add.rn.f32x2 %0, %0, %1;" : "+l"(acc) : "l"(v));
}
// pairwise fp16 add of two rows, then packed fp32 accumulate
__device__ __forceinline__ void acc_u4_pair_x2(unsigned long long* aa, uint4 v0, uint4 v1) {
    const __half2* h0 = (const __half2*)&v0;
    const __half2* h1 = (const __half2*)&v1;
    accx2(aa[0], __hadd2(h0[0], h1[0]));
    accx2(aa[1], __hadd2(h0[1], h1[1]));
    accx2(aa[2], __hadd2(h0[2], h1[2]));
    accx2(aa[3], __hadd2(h0[3], h1[3]));
}

// -------- fused prep (f2h + weight packing) + hist, block-range split --------
#define NG2   (NGn * 32)
#define ND2   (NDn * 32)
#define NWP   (4 * 2048)
#define PREP_ITEMS (NG2 + ND2 + NWP)
#define PREP_BLOCKS ((PREP_ITEMS + 255) / 256)
__global__ __launch_bounds__(256) void prep_hist(
    const float2* __restrict__ gene, __half2* __restrict__ geneH,
    const float2* __restrict__ dis,  __half2* __restrict__ disH,
    const float* __restrict__ w0, const float* __restrict__ w1,
    const float* __restrict__ w2, const float* __restrict__ w3,
    const float* __restrict__ w4, const float* __restrict__ w5,
    const float* __restrict__ w6, const float* __restrict__ w7,
    uint2* __restrict__ wPack,
    const int* __restrict__ src, const int* __restrict__ dst, int ne)
{
    int blk = blockIdx.x;
    if (blk < PREP_BLOCKS) {
        int i = blk * 256 + threadIdx.x;
        if (i < NG2) {
            float2 v = gene[i];
            geneH[i] = __floats2half2_rn(v.x, v.y);
        } else if (i < NG2 + ND2) {
            int j = i - NG2;
            float2 v = dis[j];
            disH[j] = __floats2half2_rn(v.x, v.y);
        } else if (i < PREP_ITEMS) {
            int p = i - (NG2 + ND2);
            int pi  = p >> 11;
            int rem = p & 2047;
            const float* wl;
            const float* wr;
            if      (pi == 0) { wl = w0; wr = w1; }
            else if (pi == 1) { wl = w2; wr = w3; }
            else if (pi == 2) { wl = w4; wr = w5; }
            else              { wl = w6; wr = w7; }
            int kc   = rem >> 8;
            int nt   = (rem >> 5) & 7;
            int lane = rem & 31;
            int t = lane & 3, g = lane >> 2;
            int c = nt * 8 + g;
            int k0 = kc * 16;
            int r0 = k0 + 2 * t, r2 = r0 + 8;
            float w00 = (r0 < 64)     ? wl[r0 * 64 + c]       : wr[(r0 - 64) * 64 + c];
            float w01 = (r0 + 1 < 64) ? wl[(r0 + 1) * 64 + c] : wr[(r0 - 63) * 64 + c];
            float w10 = (r2 < 64)     ? wl[r2 * 64 + c]       : wr[(r2 - 64) * 64 + c];
            float w11 = (r2 + 1 < 64) ? wl[(r2 + 1) * 64 + c] : wr[(r2 - 63) * 64 + c];
            wPack[p] = make_uint2(packh2(w00, w01), packh2(w10, w11));
        }
    } else {
        int e = (blk - PREP_BLOCKS) * 256 + threadIdx.x;
        if (e < ne) {
            atomicAdd(&g_deg[src[e]], 1);
            atomicAdd(&g_deg[NGn + dst[e]], 1);
        }
    }
}

// -------- single-pass scan (padded to 4/node) + sentinel fill --------
__global__ __launch_bounds__(1024) void scan_fused(
    int* __restrict__ off, int* __restrict__ cur, int* __restrict__ adj, int n)
{
    __shared__ int ws[32];
    __shared__ int sv[128];
    __shared__ int sExc;
    int bid = blockIdx.x;
    int tid = threadIdx.x;
    int i = bid * SCAN_B + tid;
    int v = (i < n) ? g_deg[i] : 0;
    int vp = (v + 3) & ~3;              // padded degree
    int x = vp;
    #pragma unroll
    for (int o = 1; o < 32; o <<= 1) {
        int y = __shfl_up_sync(0xFFFFFFFFu, x, o);
        if ((tid & 31) >= o) x += y;
    }
    if ((tid & 31) == 31) ws[tid >> 5] = x;
    __syncthreads();
    if (tid < 32) {
        int y = ws[tid];
        #pragma unroll
        for (int o = 1; o < 32; o <<= 1) {
            int z = __shfl_up_sync(0xFFFFFFFFu, y, o);
            if (tid >= o) y += z;
        }
        ws[tid] = y;
    }
    __syncthreads();
    if (tid >= 32) x += ws[(tid >> 5) - 1];
    if (tid == 1023) {
        atomicExch(&g_partf[bid], (x << 1) | 1);
    }
    if (tid < 128) sv[tid] = 0;
    __syncthreads();
    if (tid < bid) {
        int p;
        do { p = *(volatile int*)&g_partf[tid]; } while ((p & 1) == 0);
        sv[tid] = p >> 1;
    }
    __syncthreads();
    if (tid < 64) sv[tid] += sv[tid + 64];
    __syncthreads();
    if (tid < 32) {
        int s = sv[tid] + sv[tid + 32];
        #pragma unroll
        for (int o = 16; o; o >>= 1) s += __shfl_down_sync(0xFFFFFFFFu, s, o);
        if (tid == 0) sExc = s;
    }
    __syncthreads();
    if (i < n) {
        int inc = x + sExc;
        off[i + 1] = inc;
        int start = inc - vp;
        cur[i] = start;
        int sent = (i < NGn) ? (NDn << 7) : (NGn << 7);
        for (int k = v; k < vp; k++) adj[start + k] = sent;
        if (i == 0) off[0] = 0;
    }
}

// -------- scatter (stores PRE-SCALED byte offsets) --------
__global__ void scatter_kernel(const int* __restrict__ src, const int* __restrict__ dst,
                               int* __restrict__ cur, int* __restrict__ adj, int ne) {
    int e = blockIdx.x * blockDim.x + threadIdx.x;
    if (e < ne) {
        int s = src[e], d = dst[e];
        int p = atomicAdd(&cur[s], 1);        adj[p] = d << 7;
        int q = atomicAdd(&cur[NGn + d], 1);  adj[q] = s << 7;
    }
}

// -------- gather-mean: 4 nodes/warp, 8-lane group per node, no shuffles.
// __launch_bounds__(256, 6): cap regs so 6 CTAs/SM fit (latency-bound kernel;
// r14 measured occ 52% @ regs 46 — force higher residency). --------
__global__ __launch_bounds__(256, 6) void gather_h(
    const char* __restrict__ xgB, const char* __restrict__ xdB,
    const int* __restrict__ off, const int* __restrict__ adj,
    uint4* __restrict__ outG, uint4* __restrict__ outD)
{
    int warp = (blockIdx.x * blockDim.x + threadIdx.x) >> 5;
    if (warp * 4 >= Mn) return;
    int g = (threadIdx.x >> 3) & 3;
    int l = threadIdx.x & 7;
    int w = warp * 4 + g;
    int beg = off[w], end = off[w + 1];
    int deg = __ldg(&g_deg[w]);
    const char* __restrict__ xb = ((w < NGn) ? xdB : xgB) + (l << 4);
    const int4* __restrict__ a4 = (const int4*)(adj + beg);
    int trips = (end - beg) >> 2;

    unsigned long long aa[4];
    {
        unsigned long long z;
        asm("mov.b64 %0, {%1, %2};" : "=l"(z) : "f"(0.0f), "f"(0.0f));
        aa[0] = z; aa[1] = z; aa[2] = z; aa[3] = z;
    }
    int qi = 0;
    for (; qi + 2 <= trips; qi += 2) {
        int4 q0 = __ldg(&a4[qi]);
        int4 q1 = __ldg(&a4[qi + 1]);
        uint4 v0 = *(const uint4*)(xb + q0.x);
        uint4 v1 = *(const uint4*)(xb + q0.y);
        uint4 v2 = *(const uint4*)(xb + q0.z);
        uint4 v3 = *(const uint4*)(xb + q0.w);
        uint4 v4 = *(const uint4*)(xb + q1.x);
        uint4 v5 = *(const uint4*)(xb + q1.y);
        uint4 v6 = *(const uint4*)(xb + q1.z);
        uint4 v7 = *(const uint4*)(xb + q1.w);
        acc_u4_pair_x2(aa, v0, v1);
        acc_u4_pair_x2(aa, v2, v3);
        acc_u4_pair_x2(aa, v4, v5);
        acc_u4_pair_x2(aa, v6, v7);
    }
    if (qi < trips) {
        int4 q = __ldg(&a4[qi]);
        uint4 v0 = *(const uint4*)(xb + q.x);
        uint4 v1 = *(const uint4*)(xb + q.y);
        uint4 v2 = *(const uint4*)(xb + q.z);
        uint4 v3 = *(const uint4*)(xb + q.w);
        acc_u4_pair_x2(aa, v0, v1);
        acc_u4_pair_x2(aa, v2, v3);
    }

    float2 a0, a1, a2, a3;
    asm("mov.b64 {%0, %1}, %2;" : "=f"(a0.x), "=f"(a0.y) : "l"(aa[0]));
    asm("mov.b64 {%0, %1}, %2;" : "=f"(a1.x), "=f"(a1.y) : "l"(aa[1]));
    asm("mov.b64 {%0, %1}, %2;" : "=f"(a2.x), "=f"(a2.y) : "l"(aa[2]));
    asm("mov.b64 {%0, %1}, %2;" : "=f"(a3.x), "=f"(a3.y) : "l"(aa[3]));
    float inv = 1.0f / fmaxf((float)deg, 1.0f);
    uint4 o;
    o.x = packh2(a0.x * inv, a0.y * inv);
    o.y = packh2(a1.x * inv, a1.y * inv);
    o.z = packh2(a2.x * inv, a2.y * inv);
    o.w = packh2(a3.x * inv, a3.y * inv);
    if (w < NGn) outG[(size_t)w * 8 + l] = o;
    else         outD[(size_t)(w - NGn) * 8 + l] = o;
}

// -------- persistent per-layer SAGE linear: smem-staged A + pre-packed fp16 B --------
#define LIN_GRID 592
__global__ __launch_bounds__(256) void sage_mma2(
    const uint4* __restrict__ mD4, const uint4* __restrict__ xD4,
    const uint2* __restrict__ wpD, const float* __restrict__ bDp,
    __half2* __restrict__ outDh, int nD,
    const uint4* __restrict__ mG4, const uint4* __restrict__ xG4,
    const uint2* __restrict__ wpG, const float* __restrict__ bGp,
    __half2* __restrict__ outGh, int nG,
    int relu)
{
    __shared__ uint2 sB[2048];
    __shared__ float sBias[64];
    __shared__ uint32_t sA[128][36];

    int nbD = (nD + 127) / 128;
    int nbG = (nG + 127) / 128;
    int split = (int)(((long long)LIN_GRID * nbD) / (nbD + nbG));
    if (split < 1) split = 1;
    bool isD = ((int)blockIdx.x < split);
    const uint4* mean4  = isD ? mD4 : mG4;
    const uint4* x4     = isD ? xD4 : xG4;
    const uint2* wp     = isD ? wpD : wpG;
    const float* bias   = isD ? bDp : bGp;
    __half2* out_h      = isD ? outDh : outGh;
    int n               = isD ? nD : nG;
    int nTiles          = isD ? nbD : nbG;
    int blk0            = isD ? blockIdx.x : (blockIdx.x - split);
    int nBlkSeg         = isD ? split : (LIN_GRID - split);

    int tid = threadIdx.x;

    for (int i = tid; i < 2048; i += 256) sB[i] = __ldg(&wp[i]);
    if (tid < 64) sBias[tid] = bias[tid];

    int warp = tid >> 5, lane = tid & 31;
    int t = lane & 3, g = lane >> 2;
    int la = warp * 16 + g, lb = la + 8;

    for (int blk = blk0; blk < nTiles; blk += nBlkSeg) {
        int tileBase = blk * 128;
        int ra = tileBase + la, rb = tileBase + lb;
        bool va = ra < n, vb = rb < n;

        float c_[8][4];

        __syncthreads();
        #pragma unroll
        for (int r4 = 0; r4 < 4; r4++) {
            int flat = tid + r4 * 256;
            int row = flat >> 3, c4 = flat & 7;
            int gr = tileBase + row;
            uint4 v = __ldg(&mean4[(size_t)(gr < n ? gr : 0) * 8 + c4]);
            *(uint4*)&sA[row][c4 * 4] = v;
        }
        __syncthreads();

        #pragma unroll
        for (int nt = 0; nt < 8; nt++) {
            float b0 = sBias[nt * 8 + 2 * t];
            float b1 = sBias[nt * 8 + 2 * t + 1];
            c_[nt][0] = b0; c_[nt][1] = b1; c_[nt][2] = b0; c_[nt][3] = b1;
        }

        #pragma unroll
        for (int kc = 0; kc < 4; kc++) {
            int b8 = kc * 8;
            uint32_t a0 = sA[la][b8 + t];
            uint32_t a1 = sA[lb][b8 + t];
            uint32_t a2 = sA[la][b8 + t + 4];
            uint32_t a3 = sA[lb][b8 + t + 4];
            #pragma unroll
            for (int nt = 0; nt < 8; nt++) {
                uint2 B = sB[kc * 256 + nt * 32 + lane];
                mma16(c_[nt], a0, a1, a2, a3, B.x, B.y);
            }
        }

        __syncthreads();
        #pragma unroll
        for (int r4 = 0; r4 < 4; r4++) {
            int flat = tid + r4 * 256;
            int row = flat >> 3, c4 = flat & 7;
            int gr = tileBase + row;
            uint4 v = __ldg(&x4[(size_t)(gr < n ? gr : 0) * 8 + c4]);
            *(uint4*)&sA[row][c4 * 4] = v;
        }
        __syncthreads();

        #pragma unroll
        for (int kc = 4; kc < 8; kc++) {
            int b8 = (kc & 3) * 8;
            uint32_t a0 = sA[la][b8 + t];
            uint32_t a1 = sA[lb][b8 + t];
            uint32_t a2 = sA[la][b8 + t + 4];
            uint32_t a3 = sA[lb][b8 + t + 4];
            #pragma unroll
            for (int nt = 0; nt < 8; nt++) {
                uint2 B = sB[kc * 256 + nt * 32 + lane];
                mma16(c_[nt], a0, a1, a2, a3, B.x, B.y);
            }
        }

        #pragma unroll
        for (int nt = 0; nt < 8; nt++) {
            float c0 = c_[nt][0], c1 = c_[nt][1], c2 = c_[nt][2], c3 = c_[nt][3];
            if (relu) {
                c0 = fmaxf(c0, 0.f); c1 = fmaxf(c1, 0.f);
                c2 = fmaxf(c2, 0.f); c3 = fmaxf(c3, 0.f);
            }
            if (va) out_h[(size_t)ra * 32 + nt * 4 + t] = __floats2half2_rn(c0, c1);
            if (vb) out_h[(size_t)rb * 32 + nt * 4 + t] = __floats2half2_rn(c2, c3);
        }
    }
}

// -------- label-edge dot product + restore deg/partf zero-invariant --------
__global__ __launch_bounds__(256) void dot_h(
    const __half2* __restrict__ hg2, const __half2* __restrict__ hd2,
    const int* __restrict__ ls, const int* __restrict__ ld,
    float* __restrict__ out, int nl)
{
    int t = blockIdx.x * blockDim.x + threadIdx.x;
    if (t < Mn) g_deg[t] = 0;
    if (t < 128) g_partf[t] = 0;
    int e = t >> 3;
    if (e >= nl) return;
    int lane = t & 7;
    int a = ls[e];
    int b = ld[e];
    const uint4* pg = (const uint4*)(hg2 + (size_t)a * 32);
    const uint4* pd = (const uint4*)(hd2 + (size_t)b * 32);
    uint4 G = __ldg(&pg[lane]);
    uint4 D = __ldg(&pd[lane]);

    float acc = 0.f;
    {
        float2 g0 = __half22float2(*(__half2*)&G.x), d0 = __half22float2(*(__half2*)&D.x);
        float2 g1 = __half22float2(*(__half2*)&G.y), d1 = __half22float2(*(__half2*)&D.y);
        float2 g2 = __half22float2(*(__half2*)&G.z), d2 = __half22float2(*(__half2*)&D.z);
        float2 g3 = __half22float2(*(__half2*)&G.w), d3 = __half22float2(*(__half2*)&D.w);
        acc = g0.x * d0.x + g0.y * d0.y + g1.x * d1.x + g1.y * d1.y
            + g2.x * d2.x + g2.y * d2.y + g3.x * d3.x + g3.y * d3.y;
    }
    acc += __shfl_down_sync(0xFFFFFFFFu, acc, 4);
    acc += __shfl_down_sync(0xFFFFFFFFu, acc, 2);
    acc += __shfl_down_sync(0xFFFFFFFFu, acc, 1);
    if (lane == 0) out[e] = acc;
}

extern "C" void kernel_launch(void* const* d_in, const int* in_sizes, int n_in,
                              void* d_out, int out_size)
{
    const float* gene = nullptr;
    const float* dis  = nullptr;
    const float* w[8] = {};
    const float* b[4] = {};
    const int*   edge[2] = {};
    const int*   lab[2]  = {};
    int wi = 0, bi = 0, ei = 0, li = 0;
    int ne = 0, nl = 0;

    for (int i = 0; i < n_in; i++) {
        int sz = in_sizes[i];
        if (sz == NGn * H)          gene = (const float*)d_in[i];
        else if (sz == NDn * H)     dis  = (const float*)d_in[i];
        else if (sz == H * H)       { if (wi < 8) w[wi++] = (const float*)d_in[i]; }
        else if (sz == H)           { if (bi < 4) b[bi++] = (const float*)d_in[i]; }
        else if (sz == 1500000)     { if (ei < 2) { edge[ei++] = (const int*)d_in[i]; ne = sz; } }
        else if (sz == 500000)      { if (li < 2) { lab[li++]  = (const int*)d_in[i]; nl = sz; } }
    }

    int *off, *cur, *adj;
    __half2 *geneH, *disH, *hgH, *hdH, *mGH, *mDH;
    uint2 *wPack;
    cudaGetSymbolAddress((void**)&off,   g_off);
    cudaGetSymbolAddress((void**)&cur,   g_cur);
    cudaGetSymbolAddress((void**)&adj,   g_adj);
    cudaGetSymbolAddress((void**)&geneH, g_geneH);
    cudaGetSymbolAddress((void**)&disH,  g_disH);
    cudaGetSymbolAddress((void**)&hgH,   g_hgH);
    cudaGetSymbolAddress((void**)&hdH,   g_hdH);
    cudaGetSymbolAddress((void**)&mGH,   g_mGH);
    cudaGetSymbolAddress((void**)&mDH,   g_mDH);
    cudaGetSymbolAddress((void**)&wPack, g_wPack);

    int egrid = (ne + 255) / 256;
    int ggrid = (Mn * 8 + 255) / 256;         // 4 nodes per warp
    int ph_grid = PREP_BLOCKS + egrid;

    // ---- fused prep+hist -> padded scan (+sentinels) -> scatter ----
    prep_hist<<<ph_grid, 256>>>(
        (const float2*)gene, geneH, (const float2*)dis, disH,
        w[0], w[1], w[2], w[3], w[4], w[5], w[6], w[7], wPack,
        edge[0], edge[1], ne);
    scan_fused<<<NBLK, 1024>>>(off, cur, adj, Mn);
    scatter_kernel<<<egrid, 256>>>(edge[0], edge[1], cur, adj, ne);

    // ---- layer 1 ----
    gather_h<<<ggrid, 256>>>((const char*)geneH, (const char*)disH, off, adj,
                             (uint4*)mGH, (uint4*)mDH);
    sage_mma2<<<LIN_GRID, 256>>>(
        (const uint4*)mDH, (const uint4*)disH,  wPack + 0,    b[0], hdH, NDn,
        (const uint4*)mGH, (const uint4*)geneH, wPack + 2048, b[1], hgH, NGn, 1);

    // ---- layer 2 (fp16 outputs written in-place over hgH/hdH) ----
    gather_h<<<ggrid, 256>>>((const char*)hgH, (const char*)hdH, off, adj,
                             (uint4*)mGH, (uint4*)mDH);
    sage_mma2<<<LIN_GRID, 256>>>(
        (const uint4*)mDH, (const uint4*)hdH, wPack + 4096, b[2], hdH, NDn,
        (const uint4*)mGH, (const uint4*)hgH, wPack + 6144, b[3], hgH, NGn, 0);

    // ---- classifier (also restores deg/partf invariants) ----
    int dot_grid = (nl * 8 + 255) / 256;
    dot_h<<<dot_grid, 256>>>(hgH, hdH, lab[0], lab[1], (float*)d_out, nl);
}